// round 5
// baseline (speedup 1.0000x reference)
#include <cuda_runtime.h>

#define NBLK 144
#define NGATE 128

__device__ float g_ct[524288];   // [B=32][L=64][A=256]
__device__ float g_h[16384];     // [32][512]
__device__ float g_c[16384];
__device__ float g_cv[16384];
__device__ unsigned g_arrive;
__device__ unsigned g_epoch;

struct P {
    const float *X, *ctx, *mask; const int* cmask;
    const float *W[4], *U[4], *C[4], *bs[4];
    const float *w1c, *w1h, *b1, *w2, *b2;
    float *oh, *oc, *octx;
};

__device__ __forceinline__ float fsig(float x)  { return 1.f / (1.f + __expf(-x)); }
__device__ __forceinline__ float ftanh(float x) { return 1.f - 2.f / (1.f + __expf(2.f * x)); }

// grid barrier #n (n = 1..257). Absolute epoch values; barrier 257 resets epoch
// to 0 so every graph replay starts from identical state.
__device__ __forceinline__ void gridbar(int n) {
    __syncthreads();
    if (threadIdx.x == 0) {
        __threadfence();
        unsigned tgt = (n == 257) ? 0u : (unsigned)n;
        unsigned t = atomicAdd(&g_arrive, 1u);
        if (t == NBLK - 1) {
            atomicExch(&g_arrive, 0u);
            __threadfence();
            atomicExch(&g_epoch, tgt);
        } else {
            while (*(volatile unsigned*)&g_epoch != tgt) __nanosleep(64);
            __threadfence();
        }
    }
    __syncthreads();
}

// prologue: ctx_trans tasks (b,l) spread over all blocks
__device__ void ct_task(const P& p, float* csm, float* rsm, int blk, int tid) {
    int a4 = tid & 63, kq = tid >> 6;
    for (int tt = blk; tt < 2048; tt += NBLK) {
        int b = tt >> 6, l = tt & 63;
        __syncthreads();
        csm[tid]       = p.ctx[(b * 64 + l) * 512 + tid];
        csm[tid + 256] = p.ctx[(b * 64 + l) * 512 + tid + 256];
        __syncthreads();
        float4 acc = make_float4(0.f, 0.f, 0.f, 0.f);
        #pragma unroll 4
        for (int i = 0; i < 128; ++i) {
            int k = i * 4 + kq;
            float4 w = *(const float4*)(p.w1c + k * 256 + a4 * 4);
            float v = csm[k];
            acc.x += w.x * v; acc.y += w.y * v; acc.z += w.z * v; acc.w += w.w * v;
        }
        *(float4*)(rsm + kq * 260 + a4 * 4) = acc;
        __syncthreads();
        float s = rsm[tid] + rsm[260 + tid] + rsm[520 + tid] + rsm[780 + tid];
        g_ct[(b * 64 + l) * 256 + tid] = s + p.b1[tid];
        __syncthreads();
    }
}

__device__ __forceinline__ void gstage(float* vs, const float* src, int stride, int tid) {
    __syncthreads();
    #pragma unroll 4
    for (int i = tid; i < 16384; i += 256) {
        int bb = i >> 9, k = i & 511;
        vs[bb * 513 + k] = src[bb * stride + k];
    }
    __syncthreads();
}

__device__ __forceinline__ void gpass(float4 acc[4], const float* vs, const float* wsm,
                                      int kq, int b) {
    const float* vb = vs + b * 513;
    #pragma unroll 4
    for (int i = 0; i < 64; ++i) {
        int k = i * 8 + kq;
        float v = vb[k];
        #pragma unroll
        for (int g = 0; g < 4; ++g) {
            float4 w = *(const float4*)(wsm + (g * 512 + k) * 4);
            acc[g].x = fmaf(w.x, v, acc[g].x);
            acc[g].y = fmaf(w.y, v, acc[g].y);
            acc[g].z = fmaf(w.z, v, acc[g].z);
            acc[g].w = fmaf(w.w, v, acc[g].w);
        }
    }
}

__device__ void gate_role(const P& p, char* smem, int blk, int tid) {
    float* wsm = (float*)smem;        // 24576 f: [mat][g][k][4]
    float* vs  = wsm + 24576;         // 16416 f: [32][513]
    float* red = vs + 16416;          // 4224 f
    float* csm = vs;                  // prologue aliases
    float* rsm = vs + 512;
    const int hc = blk, b = tid & 31, kq = tid >> 5;

    // stage W/U/C slices for this h-chunk (once)
    for (int i = tid; i < 24576; i += 256) {
        int j = i & 3, k = (i >> 2) & 511, g = (i >> 11) & 3, m = i >> 13;
        const float* s = (m == 0) ? p.W[g] : (m == 1) ? p.U[g] : p.C[g];
        wsm[i] = s[k * 512 + hc * 4 + j];
    }
    int zi = blk * 256 + tid;
    if (zi < 16384) { g_h[zi] = 0.f; g_c[zi] = 0.f; }
    ct_task(p, csm, rsm, blk, tid);
    gridbar(1);

    float4 b0[4];
    #pragma unroll
    for (int g = 0; g < 4; ++g) b0[g] = *(const float4*)(p.bs[g] + hc * 4);

    int bar = 2;
    for (int t = 0; t < 128; ++t) {
        gridbar(bar); bar++;                      // h,c,cv of t-1 sealed
        float4 acc[4];
        #pragma unroll
        for (int g = 0; g < 4; ++g)
            acc[g] = (kq == 0) ? b0[g] : make_float4(0.f, 0.f, 0.f, 0.f);
        gstage(vs, p.X + t * 512, 65536, tid);
        gpass(acc, vs, wsm, kq, b);               // x_t @ W
        gstage(vs, g_h, 512, tid);
        gpass(acc, vs, wsm + 8192, kq, b);        // h @ U
        gridbar(bar); bar++;                      // cv ready
        gstage(vs, g_cv, 512, tid);
        gpass(acc, vs, wsm + 16384, kq, b);       // cv @ C
        __syncthreads();
        #pragma unroll
        for (int g = 0; g < 4; ++g) {
            red[((g * 4 + 0) * 8 + kq) * 33 + b] = acc[g].x;
            red[((g * 4 + 1) * 8 + kq) * 33 + b] = acc[g].y;
            red[((g * 4 + 2) * 8 + kq) * 33 + b] = acc[g].z;
            red[((g * 4 + 3) * 8 + kq) * 33 + b] = acc[g].w;
        }
        __syncthreads();
        if (tid < 128) {
            int bb = tid >> 2, j = tid & 3, h = hc * 4 + j;
            float pre[4];
            #pragma unroll
            for (int g = 0; g < 4; ++g) {
                int o = g * 4 + j;
                float s = 0.f;
                #pragma unroll
                for (int q = 0; q < 8; ++q) s += red[(o * 8 + q) * 33 + bb];
                pre[g] = s;
            }
            float iv = fsig(pre[0]), fv = fsig(pre[1]);
            float gv = ftanh(pre[2]), ov = fsig(pre[3]);
            float co = g_c[bb * 512 + h], ho = g_h[bb * 512 + h];
            float cn = fv * co + iv * gv;
            float hn = ov * ftanh(cn);
            float m = p.mask[bb * 128 + t];
            hn = (1.f - m) * ho + m * hn;
            cn = (1.f - m) * co + m * cn;
            g_h[bb * 512 + h] = hn;
            g_c[bb * 512 + h] = cn;
            p.oh[(bb * 128 + t) * 512 + h] = hn;
            p.oc[(bb * 128 + t) * 512 + h] = cn;
        }
    }
}

__device__ void att_role(const P& p, char* smem, int blk, int tid) {
    float* ctsm = (float*)smem;       // 32768 f: [2][64][256]
    float* hsm  = ctsm + 32768;       // 1024
    float* hwsm = hsm + 1024;         // 512: [2][256]
    float* redh = hwsm + 512;         // 2080: [2][4][260]
    float* w2sm = redh + 2080;        // 256
    float* esm  = w2sm + 256;         // 128
    float* av   = esm + 128;          // 128
    float* ssum = av + 128;           // 2 (+pad)
    float* csm  = ssum + 16;          // 512 (prologue)
    float* rsm  = csm + 512;          // 1040
    const int b0 = (blk - NGATE) * 2;
    const int a4 = tid & 63, kq = tid >> 6;
    const int ww = tid >> 5, lane = tid & 31;

    ct_task(p, csm, rsm, blk, tid);
    gridbar(1);
    for (int i = tid; i < 32768; i += 256) ctsm[i] = g_ct[b0 * 16384 + i];
    w2sm[tid] = p.w2[tid];
    const float b2v = p.b2[0];
    const float cm0 = (float)p.cmask[b0 * 64 + 0]; (void)cm0;

    int bar = 2;
    for (int t = 0; t < 128; ++t) {
        gridbar(bar); bar++;
        #pragma unroll
        for (int q = 0; q < 4; ++q)
            hsm[q * 256 + tid] = g_h[b0 * 512 + q * 256 + tid];
        __syncthreads();
        // hW for both batches, shared weight loads
        float4 ac0 = make_float4(0.f, 0.f, 0.f, 0.f);
        float4 ac1 = make_float4(0.f, 0.f, 0.f, 0.f);
        #pragma unroll 4
        for (int i = 0; i < 128; ++i) {
            int k = i * 4 + kq;
            float4 w = *(const float4*)(p.w1h + k * 256 + a4 * 4);
            float v0 = hsm[k], v1 = hsm[512 + k];
            ac0.x += w.x * v0; ac0.y += w.y * v0; ac0.z += w.z * v0; ac0.w += w.w * v0;
            ac1.x += w.x * v1; ac1.y += w.y * v1; ac1.z += w.z * v1; ac1.w += w.w * v1;
        }
        *(float4*)(redh + kq * 260 + a4 * 4) = ac0;
        *(float4*)(redh + 1040 + kq * 260 + a4 * 4) = ac1;
        __syncthreads();
        hwsm[tid]       = redh[tid] + redh[260 + tid] + redh[520 + tid] + redh[780 + tid];
        hwsm[256 + tid] = redh[1040 + tid] + redh[1300 + tid] + redh[1560 + tid] + redh[1820 + tid];
        __syncthreads();
        // scores: warp ww handles l = ww*8 + lq for both batches
        #pragma unroll
        for (int bb = 0; bb < 2; ++bb) {
            for (int lq = 0; lq < 8; ++lq) {
                int l = ww * 8 + lq;
                float s = 0.f;
                #pragma unroll
                for (int j = 0; j < 8; ++j) {
                    int a = j * 32 + lane;
                    float x = ctsm[(bb * 64 + l) * 256 + a] + hwsm[bb * 256 + a];
                    s = fmaf(ftanh(x), w2sm[a], s);
                }
                #pragma unroll
                for (int o = 16; o; o >>= 1) s += __shfl_xor_sync(0xffffffffu, s, o);
                if (lane == 0)
                    esm[bb * 64 + l] = __expf(s + b2v) * (float)p.cmask[(b0 + bb) * 64 + l];
            }
        }
        __syncthreads();
        if (tid < 2) {
            float s = 0.f;
            for (int l = 0; l < 64; ++l) s += esm[tid * 64 + l];
            ssum[tid] = s;
        }
        __syncthreads();
        if (tid < 128) av[tid] = esm[tid] / ssum[tid >> 6];
        __syncthreads();
        // ctx_vec for both batches
        float2 c0 = make_float2(0.f, 0.f), c1 = make_float2(0.f, 0.f);
        #pragma unroll 4
        for (int l = 0; l < 64; ++l) {
            float a0 = av[l], a1 = av[64 + l];
            float2 x0 = *(const float2*)(p.ctx + (b0 * 64 + l) * 512 + tid * 2);
            float2 x1 = *(const float2*)(p.ctx + ((b0 + 1) * 64 + l) * 512 + tid * 2);
            c0.x += a0 * x0.x; c0.y += a0 * x0.y;
            c1.x += a1 * x1.x; c1.y += a1 * x1.y;
        }
        *(float2*)(g_cv + b0 * 512 + tid * 2) = c0;
        *(float2*)(g_cv + (b0 + 1) * 512 + tid * 2) = c1;
        *(float2*)(p.octx + (b0 * 128 + t) * 512 + tid * 2) = c0;
        *(float2*)(p.octx + ((b0 + 1) * 128 + t) * 512 + tid * 2) = c1;
        gridbar(bar); bar++;   // cv published; idle through gate phase B
    }
}

extern "C" __global__ void __launch_bounds__(256, 1) cond_lstm(P p) {
    extern __shared__ char smem[];
    if (blockIdx.x < NGATE) gate_role(p, smem, blockIdx.x, threadIdx.x);
    else                    att_role(p, smem, blockIdx.x, threadIdx.x);
}

#define SMEM_BYTES 180864

extern "C" void kernel_launch(void* const* d_in, const int* in_sizes, int n_in,
                              void* d_out, int out_size) {
    (void)in_sizes; (void)n_in; (void)out_size;
    P p;
    p.X     = (const float*)d_in[0];
    p.ctx   = (const float*)d_in[1];
    p.mask  = (const float*)d_in[2];
    p.cmask = (const int*)d_in[3];
    for (int g = 0; g < 4; ++g) {
        p.W[g]  = (const float*)d_in[4 + 4 * g];
        p.U[g]  = (const float*)d_in[5 + 4 * g];
        p.C[g]  = (const float*)d_in[6 + 4 * g];
        p.bs[g] = (const float*)d_in[7 + 4 * g];
    }
    p.w1c = (const float*)d_in[20];
    p.w1h = (const float*)d_in[21];
    p.b1  = (const float*)d_in[22];
    p.w2  = (const float*)d_in[23];
    p.b2  = (const float*)d_in[24];
    float* out = (float*)d_out;
    p.oh   = out;
    p.oc   = out + 32 * 128 * 512;
    p.octx = out + 2 * 32 * 128 * 512;

    cudaFuncSetAttribute(cond_lstm, cudaFuncAttributeMaxDynamicSharedMemorySize, SMEM_BYTES);
    cond_lstm<<<NBLK, 256, SMEM_BYTES>>>(p);
}

// round 6
// speedup vs baseline: 1.3910x; 1.3910x over previous
#include <cuda_runtime.h>

#define NBLK 144
#define NGATE 128
#define NT 512

__device__ float g_ct[524288];   // [B=32][L=64][A=256]
__device__ float g_h[16384];     // [32][512]
__device__ float g_c[16384];
__device__ float g_cv[16384];
__device__ unsigned g_flag[NBLK * 8];  // padded 32B apart
__device__ unsigned g_epoch;

struct P {
    const float *X, *ctx, *mask; const int* cmask;
    const float *W[4], *U[4], *C[4], *bs[4];
    const float *w1c, *w1h, *b1, *w2, *b2;
    float *oh, *oc, *octx;
};

__device__ __forceinline__ float fsig(float x)  { return 1.f / (1.f + __expf(-x)); }
__device__ __forceinline__ float ftanh(float x) { return 1.f - 2.f / (1.f + __expf(2.f * x)); }

// Flag-array grid barrier #n (1..257). Contention-free arrival (own-slot STG),
// block 0 / warp 0 is the releaser. Barrier 257 writes 0 everywhere so every
// graph replay starts from identical state.
__device__ __forceinline__ void gridbar(int n) {
    unsigned fv = (n == 257) ? 0u : (unsigned)n;
    __syncthreads();
    if (blockIdx.x == 0) {
        if (threadIdx.x < 32) {
            if (threadIdx.x == 0) { __threadfence(); *(volatile unsigned*)&g_flag[0] = fv; }
            for (;;) {
                bool ok = true;
                #pragma unroll
                for (int j = 0; j < 5; ++j) {
                    int bk = threadIdx.x + j * 32;
                    if (bk < NBLK) ok &= (*(volatile unsigned*)&g_flag[bk * 8] == fv);
                }
                if (__all_sync(0xffffffffu, ok)) break;
                __nanosleep(32);
            }
            __threadfence();
            if (threadIdx.x == 0) *(volatile unsigned*)&g_epoch = fv;
        }
    } else if (threadIdx.x == 0) {
        __threadfence();
        *(volatile unsigned*)&g_flag[blockIdx.x * 8] = fv;
        while (*(volatile unsigned*)&g_epoch != fv) __nanosleep(32);
        __threadfence();
    }
    __syncthreads();
}

// prologue: ctx_trans tasks (b,l) spread over all blocks; csm[512], rsm[520]
__device__ void ct_task(const P& p, float* csm, float* rsm, int blk, int tid) {
    const int a = tid & 255, kq = tid >> 8;
    for (int tt = blk; tt < 2048; tt += NBLK) {
        int b = tt >> 6, l = tt & 63;
        __syncthreads();
        csm[tid] = p.ctx[(b * 64 + l) * 512 + tid];
        __syncthreads();
        float acc = 0.f;
        #pragma unroll 8
        for (int i = 0; i < 256; ++i) {
            int k = kq * 256 + i;
            acc = fmaf(p.w1c[k * 256 + a], csm[k], acc);
        }
        rsm[kq * 260 + a] = acc;
        __syncthreads();
        if (tid < 256) g_ct[(b * 64 + l) * 256 + tid] = rsm[tid] + rsm[260 + tid] + p.b1[tid];
        __syncthreads();
    }
}

// stage 32x512 source rows into vs[32][513] via float4 L2 loads
__device__ __forceinline__ void gstage(float* vs, const float* src, int stride, int tid) {
    __syncthreads();
    #pragma unroll
    for (int j = 0; j < 8; ++j) {
        int i4 = tid + j * NT;          // quad index 0..4095
        int bb = i4 >> 7;
        int k4 = (i4 & 127) * 4;
        float4 v = __ldcg((const float4*)(src + bb * stride + k4));
        float* d = vs + bb * 513 + k4;
        d[0] = v.x; d[1] = v.y; d[2] = v.z; d[3] = v.w;
    }
    __syncthreads();
}

__device__ __forceinline__ void gpass(float4 acc[4], const float* vs, const float* wsm,
                                      int kq, int b) {
    const float* vb = vs + b * 513;
    #pragma unroll 8
    for (int i = 0; i < 32; ++i) {
        int k = i * 16 + kq;
        float v = vb[k];
        #pragma unroll
        for (int g = 0; g < 4; ++g) {
            float4 w = *(const float4*)(wsm + (g * 512 + k) * 4);
            acc[g].x = fmaf(w.x, v, acc[g].x);
            acc[g].y = fmaf(w.y, v, acc[g].y);
            acc[g].z = fmaf(w.z, v, acc[g].z);
            acc[g].w = fmaf(w.w, v, acc[g].w);
        }
    }
}

__device__ void gate_role(const P& p, char* smem, int blk, int tid) {
    float* wsm = (float*)smem;        // 24576 f  [mat][g][k][4]
    float* vs  = wsm + 24576;         // 16416 f  [32][513]
    float* red = vs;                  // alias (8448 f)
    float* csm = vs;                  // prologue alias
    float* rsm = vs + 512;
    const int hc = blk, b = tid & 31, kq = tid >> 5;

    for (int i = tid; i < 24576; i += NT) {
        int j = i & 3, k = (i >> 2) & 511, g = (i >> 11) & 3, m = i >> 13;
        const float* s = (m == 0) ? p.W[g] : (m == 1) ? p.U[g] : p.C[g];
        wsm[i] = s[k * 512 + hc * 4 + j];
    }
    int zi = blk * NT + tid;
    if (zi < 16384) { g_h[zi] = 0.f; g_c[zi] = 0.f; }
    ct_task(p, csm, rsm, blk, tid);
    gridbar(1);

    float4 b0[4];
    #pragma unroll
    for (int g = 0; g < 4; ++g) b0[g] = *(const float4*)(p.bs[g] + hc * 4);

    int bar = 2;
    for (int t = 0; t < 128; ++t) {
        gstage(vs, p.X + t * 512, 65536, tid);    // X(t): pre-stage, hides behind barrier
        gridbar(bar); bar++;                      // h,c,cv of t-1 sealed
        float4 acc[4];
        #pragma unroll
        for (int g = 0; g < 4; ++g)
            acc[g] = (kq == 0) ? b0[g] : make_float4(0.f, 0.f, 0.f, 0.f);
        gpass(acc, vs, wsm, kq, b);               // x_t @ W
        gstage(vs, g_h, 512, tid);
        gpass(acc, vs, wsm + 8192, kq, b);        // h @ U
        gridbar(bar); bar++;                      // cv ready
        gstage(vs, g_cv, 512, tid);
        gpass(acc, vs, wsm + 16384, kq, b);       // cv @ C
        __syncthreads();
        #pragma unroll
        for (int g = 0; g < 4; ++g) {
            red[((g * 4 + 0) * 16 + kq) * 33 + b] = acc[g].x;
            red[((g * 4 + 1) * 16 + kq) * 33 + b] = acc[g].y;
            red[((g * 4 + 2) * 16 + kq) * 33 + b] = acc[g].z;
            red[((g * 4 + 3) * 16 + kq) * 33 + b] = acc[g].w;
        }
        __syncthreads();
        if (tid < 128) {
            int bb = tid >> 2, j = tid & 3, h = hc * 4 + j;
            float pre[4];
            #pragma unroll
            for (int g = 0; g < 4; ++g) {
                int o = g * 4 + j;
                float s = 0.f;
                #pragma unroll
                for (int q = 0; q < 16; ++q) s += red[(o * 16 + q) * 33 + bb];
                pre[g] = s;
            }
            float iv = fsig(pre[0]), fv = fsig(pre[1]);
            float gv = ftanh(pre[2]), ov = fsig(pre[3]);
            float co = __ldcg(&g_c[bb * 512 + h]), ho = __ldcg(&g_h[bb * 512 + h]);
            float cn = fv * co + iv * gv;
            float hn = ov * ftanh(cn);
            float m = p.mask[bb * 128 + t];
            hn = (1.f - m) * ho + m * hn;
            cn = (1.f - m) * co + m * cn;
            g_h[bb * 512 + h] = hn;
            g_c[bb * 512 + h] = cn;
            p.oh[(bb * 128 + t) * 512 + h] = hn;
            p.oc[(bb * 128 + t) * 512 + h] = cn;
        }
    }
}

__device__ void att_role(const P& p, char* smem, int blk, int tid) {
    float* ctsm = (float*)smem;       // 32768 f  [2][64][256]
    float* hsm  = ctsm + 32768;       // 1024
    float* redh = hsm + 1024;         // 4160: [2][8][260]
    float* hwsm = redh + 4160;        // 512:  [2][256]
    float* w2sm = hwsm + 512;         // 256
    float* esm  = w2sm + 256;         // 128
    float* av   = esm + 128;          // 128
    float* ssum = av + 128;           // 16
    float* csm  = ctsm;               // prologue alias
    float* rsm  = ctsm + 512;
    const int b0 = (blk - NGATE) * 2;
    const int a4 = tid & 63, kq8 = tid >> 6;    // kq8 0..7
    const int ww = tid >> 5, lane = tid & 31;

    ct_task(p, csm, rsm, blk, tid);
    gridbar(1);
    for (int i = tid; i < 32768; i += NT) ctsm[i] = __ldcg(&g_ct[b0 * 16384 + i]);
    if (tid < 256) w2sm[tid] = p.w2[tid];
    const float b2v = p.b2[0];

    int bar = 2;
    for (int t = 0; t < 128; ++t) {
        gridbar(bar); bar++;
        hsm[tid]       = __ldcg(&g_h[b0 * 512 + tid]);
        hsm[512 + tid] = __ldcg(&g_h[b0 * 512 + 512 + tid]);
        __syncthreads();
        // hW for both batches; thread (a4, kq8) covers k = i*8+kq8
        float4 ac0 = make_float4(0.f, 0.f, 0.f, 0.f);
        float4 ac1 = make_float4(0.f, 0.f, 0.f, 0.f);
        #pragma unroll 4
        for (int i = 0; i < 64; ++i) {
            int k = i * 8 + kq8;
            float4 w = __ldg((const float4*)(p.w1h + k * 256 + a4 * 4));
            float v0 = hsm[k], v1 = hsm[512 + k];
            ac0.x += w.x * v0; ac0.y += w.y * v0; ac0.z += w.z * v0; ac0.w += w.w * v0;
            ac1.x += w.x * v1; ac1.y += w.y * v1; ac1.z += w.z * v1; ac1.w += w.w * v1;
        }
        *(float4*)(redh + kq8 * 260 + a4 * 4)              = ac0;
        *(float4*)(redh + 2080 + kq8 * 260 + a4 * 4)       = ac1;
        __syncthreads();
        {
            int bb = tid >> 8, a = tid & 255;
            float s = 0.f;
            #pragma unroll
            for (int q = 0; q < 8; ++q) s += redh[bb * 2080 + q * 260 + a];
            hwsm[bb * 256 + a] = s;
        }
        __syncthreads();
        // scores: warp ww -> l = ww*4 + lq, both batches
        #pragma unroll
        for (int bb = 0; bb < 2; ++bb) {
            #pragma unroll
            for (int lq = 0; lq < 4; ++lq) {
                int l = ww * 4 + lq;
                float s = 0.f;
                #pragma unroll
                for (int j = 0; j < 8; ++j) {
                    int a = j * 32 + lane;
                    float x = ctsm[(bb * 64 + l) * 256 + a] + hwsm[bb * 256 + a];
                    s = fmaf(ftanh(x), w2sm[a], s);
                }
                #pragma unroll
                for (int o = 16; o; o >>= 1) s += __shfl_xor_sync(0xffffffffu, s, o);
                if (lane == 0)
                    esm[bb * 64 + l] = __expf(s + b2v) * (float)__ldg(&p.cmask[(b0 + bb) * 64 + l]);
            }
        }
        __syncthreads();
        if (tid < 2) {
            float s = 0.f;
            for (int l = 0; l < 64; ++l) s += esm[tid * 64 + l];
            ssum[tid] = s;
        }
        __syncthreads();
        if (tid < 128) av[tid] = esm[tid] / ssum[tid >> 6];
        __syncthreads();
        // ctx_vec: thread owns one d for both batches
        float c0 = 0.f, c1 = 0.f;
        #pragma unroll 8
        for (int l = 0; l < 64; ++l) {
            float a0 = av[l], a1 = av[64 + l];
            c0 = fmaf(a0, __ldg(&p.ctx[(b0 * 64 + l) * 512 + tid]), c0);
            c1 = fmaf(a1, __ldg(&p.ctx[((b0 + 1) * 64 + l) * 512 + tid]), c1);
        }
        g_cv[b0 * 512 + tid]        = c0;
        g_cv[(b0 + 1) * 512 + tid]  = c1;
        p.octx[(b0 * 128 + t) * 512 + tid]       = c0;
        p.octx[((b0 + 1) * 128 + t) * 512 + tid] = c1;
        gridbar(bar); bar++;   // cv published; idle through gate phase B
    }
}

extern "C" __global__ void __launch_bounds__(NT, 1) cond_lstm(P p) {
    extern __shared__ char smem[];
    if (blockIdx.x < NGATE) gate_role(p, smem, blockIdx.x, threadIdx.x);
    else                    att_role(p, smem, blockIdx.x, threadIdx.x);
}

#define SMEM_BYTES 163968

extern "C" void kernel_launch(void* const* d_in, const int* in_sizes, int n_in,
                              void* d_out, int out_size) {
    (void)in_sizes; (void)n_in; (void)out_size;
    P p;
    p.X     = (const float*)d_in[0];
    p.ctx   = (const float*)d_in[1];
    p.mask  = (const float*)d_in[2];
    p.cmask = (const int*)d_in[3];
    for (int g = 0; g < 4; ++g) {
        p.W[g]  = (const float*)d_in[4 + 4 * g];
        p.U[g]  = (const float*)d_in[5 + 4 * g];
        p.C[g]  = (const float*)d_in[6 + 4 * g];
        p.bs[g] = (const float*)d_in[7 + 4 * g];
    }
    p.w1c = (const float*)d_in[20];
    p.w1h = (const float*)d_in[21];
    p.b1  = (const float*)d_in[22];
    p.w2  = (const float*)d_in[23];
    p.b2  = (const float*)d_in[24];
    float* out = (float*)d_out;
    p.oh   = out;
    p.oc   = out + 32 * 128 * 512;
    p.octx = out + 2 * 32 * 128 * 512;

    cudaFuncSetAttribute(cond_lstm, cudaFuncAttributeMaxDynamicSharedMemorySize, SMEM_BYTES);
    cond_lstm<<<NBLK, NT, SMEM_BYTES>>>(p);
}

// round 7
// speedup vs baseline: 1.4831x; 1.0662x over previous
#include <cuda_runtime.h>

#define NBLK 144
#define NGATE 128
#define NT 1024

__device__ float g_ct[524288];   // [B=32][L=64][A=256]
__device__ float g_h[16384];     // [32][512]
__device__ float g_c[16384];
__device__ float g_cv[16384];
__device__ unsigned g_flag[NBLK * 8];
__device__ unsigned g_epoch;

struct P {
    const float *X, *ctx, *mask; const int* cmask;
    const float *W[4], *U[4], *C[4], *bs[4];
    const float *w1c, *w1h, *b1, *w2, *b2;
    float *oh, *oc, *octx;
};

__device__ __forceinline__ float fsig(float x)  { return 1.f / (1.f + __expf(-x)); }
__device__ __forceinline__ float ftanh(float x) { return 1.f - 2.f / (1.f + __expf(2.f * x)); }

// Flag-array grid barrier #n (1..257). Own-slot arrival, block 0 warp 0 releases.
// Barrier 257 writes 0 so every graph replay starts from identical state.
__device__ __forceinline__ void gridbar(int n) {
    unsigned fv = (n == 257) ? 0u : (unsigned)n;
    __syncthreads();
    if (blockIdx.x == 0) {
        if (threadIdx.x < 32) {
            if (threadIdx.x == 0) { __threadfence(); *(volatile unsigned*)&g_flag[0] = fv; }
            for (;;) {
                bool ok = true;
                #pragma unroll
                for (int j = 0; j < 5; ++j) {
                    int bk = threadIdx.x + j * 32;
                    if (bk < NBLK) ok &= (*(volatile unsigned*)&g_flag[bk * 8] == fv);
                }
                if (__all_sync(0xffffffffu, ok)) break;
                __nanosleep(32);
            }
            __threadfence();
            if (threadIdx.x == 0) *(volatile unsigned*)&g_epoch = fv;
        }
    } else if (threadIdx.x == 0) {
        __threadfence();
        *(volatile unsigned*)&g_flag[blockIdx.x * 8] = fv;
        while (*(volatile unsigned*)&g_epoch != fv) __nanosleep(32);
        __threadfence();
    }
    __syncthreads();
}

// prologue ctx_trans; csm[512], rsm[4*260]
__device__ void ct_task(const P& p, float* csm, float* rsm, int blk, int tid) {
    const int a = tid & 255, kq = tid >> 8;   // kq 0..3
    for (int tt = blk; tt < 2048; tt += NBLK) {
        int b = tt >> 6, l = tt & 63;
        __syncthreads();
        if (tid < 512) csm[tid] = p.ctx[(b * 64 + l) * 512 + tid];
        __syncthreads();
        float acc = 0.f;
        #pragma unroll 8
        for (int i = 0; i < 128; ++i) {
            int k = kq * 128 + i;
            acc = fmaf(p.w1c[k * 256 + a], csm[k], acc);
        }
        rsm[kq * 260 + a] = acc;
        __syncthreads();
        if (tid < 256)
            g_ct[(b * 64 + l) * 256 + tid] =
                rsm[tid] + rsm[260 + tid] + rsm[520 + tid] + rsm[780 + tid] + p.b1[tid];
        __syncthreads();
    }
}

// stage 32x512 rows into vs[32][513]
__device__ __forceinline__ void gstage(float* vs, const float* src, int stride, int tid) {
    __syncthreads();
    #pragma unroll
    for (int j = 0; j < 4; ++j) {
        int i4 = tid + j * NT;
        int bb = i4 >> 7;
        int k4 = (i4 & 127) * 4;
        float4 v = __ldcg((const float4*)(src + bb * stride + k4));
        float* d = vs + bb * 513 + k4;
        d[0] = v.x; d[1] = v.y; d[2] = v.z; d[3] = v.w;
    }
    __syncthreads();
}

// 16 k-values per thread (kq 0..31)
__device__ __forceinline__ void gpass(float4 acc[4], const float* vs, const float* wsm,
                                      int kq, int b) {
    const float* vb = vs + b * 513;
    #pragma unroll 4
    for (int i = 0; i < 16; ++i) {
        int k = i * 32 + kq;
        float v = vb[k];
        #pragma unroll
        for (int g = 0; g < 4; ++g) {
            float4 w = *(const float4*)(wsm + (g * 512 + k) * 4);
            acc[g].x = fmaf(w.x, v, acc[g].x);
            acc[g].y = fmaf(w.y, v, acc[g].y);
            acc[g].z = fmaf(w.z, v, acc[g].z);
            acc[g].w = fmaf(w.w, v, acc[g].w);
        }
    }
}

__device__ void gate_role(const P& p, char* smem, int blk, int tid) {
    float* wsm = (float*)smem;        // 24576 f [mat][g][k][4]
    float* vs  = wsm + 24576;         // 16416 f [32][513]
    float* red = vs;                  // alias, 8448 f used
    float* csm = vs;                  // prologue alias
    float* rsm = vs + 512;
    const int hc = blk, b = tid & 31, kq = tid >> 5;   // kq 0..31

    for (int i = tid; i < 24576; i += NT) {
        int j = i & 3, k = (i >> 2) & 511, g = (i >> 11) & 3, m = i >> 13;
        const float* s = (m == 0) ? p.W[g] : (m == 1) ? p.U[g] : p.C[g];
        wsm[i] = s[k * 512 + hc * 4 + j];
    }
    int zi = blk * NT + tid;
    if (zi < 16384) { g_h[zi] = 0.f; g_c[zi] = 0.f; }
    ct_task(p, csm, rsm, blk, tid);
    gridbar(1);

    float4 b0[4];
    #pragma unroll
    for (int g = 0; g < 4; ++g) b0[g] = *(const float4*)(p.bs[g] + hc * 4);

    int bar = 2;
    for (int t = 0; t < 128; ++t) {
        gstage(vs, p.X + t * 512, 65536, tid);    // pre-stage X(t) behind barrier wait
        gridbar(bar); bar++;                      // h,c,cv of t-1 sealed
        float4 acc[4];
        #pragma unroll
        for (int g = 0; g < 4; ++g)
            acc[g] = (kq == 0) ? b0[g] : make_float4(0.f, 0.f, 0.f, 0.f);
        gpass(acc, vs, wsm, kq, b);               // x_t @ W
        gstage(vs, g_h, 512, tid);
        gpass(acc, vs, wsm + 8192, kq, b);        // h @ U
        gridbar(bar); bar++;                      // cv ready
        gstage(vs, g_cv, 512, tid);
        gpass(acc, vs, wsm + 16384, kq, b);       // cv @ C
        __syncthreads();
        // two-phase reduction over kq (32 partials -> 16 -> final)
        if (kq >= 16) {
            int q = kq - 16;
            #pragma unroll
            for (int g = 0; g < 4; ++g) {
                red[((g * 4 + 0) * 16 + q) * 33 + b] = acc[g].x;
                red[((g * 4 + 1) * 16 + q) * 33 + b] = acc[g].y;
                red[((g * 4 + 2) * 16 + q) * 33 + b] = acc[g].z;
                red[((g * 4 + 3) * 16 + q) * 33 + b] = acc[g].w;
            }
        }
        __syncthreads();
        if (kq < 16) {
            #pragma unroll
            for (int g = 0; g < 4; ++g) {
                red[((g * 4 + 0) * 16 + kq) * 33 + b] += acc[g].x;
                red[((g * 4 + 1) * 16 + kq) * 33 + b] += acc[g].y;
                red[((g * 4 + 2) * 16 + kq) * 33 + b] += acc[g].z;
                red[((g * 4 + 3) * 16 + kq) * 33 + b] += acc[g].w;
            }
        }
        __syncthreads();
        if (tid < 128) {
            int bb = tid >> 2, j = tid & 3, h = hc * 4 + j;
            float pre[4];
            #pragma unroll
            for (int g = 0; g < 4; ++g) {
                int o = g * 4 + j;
                float s = 0.f;
                #pragma unroll
                for (int q = 0; q < 16; ++q) s += red[(o * 16 + q) * 33 + bb];
                pre[g] = s;
            }
            float iv = fsig(pre[0]), fv = fsig(pre[1]);
            float gv = ftanh(pre[2]), ov = fsig(pre[3]);
            float co = __ldcg(&g_c[bb * 512 + h]), ho = __ldcg(&g_h[bb * 512 + h]);
            float cn = fv * co + iv * gv;
            float hn = ov * ftanh(cn);
            float m = p.mask[bb * 128 + t];
            hn = (1.f - m) * ho + m * hn;
            cn = (1.f - m) * co + m * cn;
            g_h[bb * 512 + h] = hn;
            g_c[bb * 512 + h] = cn;
            p.oh[(bb * 128 + t) * 512 + h] = hn;
            p.oc[(bb * 128 + t) * 512 + h] = cn;
        }
    }
}

__device__ void att_role(const P& p, char* smem, int blk, int tid) {
    float* ctsm = (float*)smem;       // 32768 f [2][64][256]
    float* hsm  = ctsm + 32768;       // 1024
    float* redh = hsm + 1024;         // 4128: [2][8][258]
    float* hwsm = redh + 4128;        // 512: [2][256]
    float* w2sm = hwsm + 512;         // 256
    float* esm  = w2sm + 256;         // 128
    float* av   = esm + 128;          // 128
    float* ssum = av + 128;           // 16
    float* csm  = ctsm;               // prologue alias
    float* rsm  = ctsm + 512;
    const int b0 = (blk - NGATE) * 2;
    const int a2 = tid & 127, kq = tid >> 7;   // kq 0..7
    const int ww = tid >> 5, lane = tid & 31;

    ct_task(p, csm, rsm, blk, tid);
    gridbar(1);
    for (int i = tid; i < 32768; i += NT) ctsm[i] = __ldcg(&g_ct[b0 * 16384 + i]);
    if (tid < 256) w2sm[tid] = p.w2[tid];
    const float b2v = p.b2[0];

    int bar = 2;
    for (int t = 0; t < 128; ++t) {
        gridbar(bar); bar++;
        hsm[tid] = __ldcg(&g_h[b0 * 512 + tid]);   // both batches, 1024 floats
        __syncthreads();
        // hW: thread (a2, kq): float2 over a = a2*2..+1, k = i*8+kq
        float2 ac0 = make_float2(0.f, 0.f), ac1 = make_float2(0.f, 0.f);
        #pragma unroll 8
        for (int i = 0; i < 64; ++i) {
            int k = i * 8 + kq;
            float2 w = __ldg((const float2*)(p.w1h + k * 256 + a2 * 2));
            float v0 = hsm[k], v1 = hsm[512 + k];
            ac0.x += w.x * v0; ac0.y += w.y * v0;
            ac1.x += w.x * v1; ac1.y += w.y * v1;
        }
        *(float2*)(redh + kq * 258 + a2 * 2)        = ac0;
        *(float2*)(redh + 2064 + kq * 258 + a2 * 2) = ac1;
        __syncthreads();
        if (tid < 512) {
            int bb = tid >> 8, a = tid & 255;
            float s = 0.f;
            #pragma unroll
            for (int q = 0; q < 8; ++q) s += redh[bb * 2064 + q * 258 + a];
            hwsm[bb * 256 + a] = s;
        }
        __syncthreads();
        // scores: warp ww -> bb = ww>>4, l = (ww&15)*4 + lq
        {
            int bb = ww >> 4;
            #pragma unroll
            for (int lq = 0; lq < 4; ++lq) {
                int l = (ww & 15) * 4 + lq;
                float s = 0.f;
                #pragma unroll
                for (int j = 0; j < 8; ++j) {
                    int a = j * 32 + lane;
                    float x = ctsm[(bb * 64 + l) * 256 + a] + hwsm[bb * 256 + a];
                    s = fmaf(ftanh(x), w2sm[a], s);
                }
                #pragma unroll
                for (int o = 16; o; o >>= 1) s += __shfl_xor_sync(0xffffffffu, s, o);
                if (lane == 0)
                    esm[bb * 64 + l] = __expf(s + b2v) * (float)__ldg(&p.cmask[(b0 + bb) * 64 + l]);
            }
        }
        __syncthreads();
        if (tid < 2) {
            float s = 0.f;
            for (int l = 0; l < 64; ++l) s += esm[tid * 64 + l];
            ssum[tid] = s;
        }
        __syncthreads();
        if (tid < 128) av[tid] = esm[tid] / ssum[tid >> 6];
        __syncthreads();
        // ctx_vec: thread owns (bb = tid>>9, d = tid&511)
        {
            int bb = tid >> 9, d = tid & 511;
            float c = 0.f;
            const float* cp = p.ctx + ((b0 + bb) * 64) * 512 + d;
            const float* ap = av + bb * 64;
            #pragma unroll 8
            for (int l = 0; l < 64; ++l)
                c = fmaf(ap[l], __ldg(cp + l * 512), c);
            g_cv[(b0 + bb) * 512 + d] = c;
            p.octx[((b0 + bb) * 128 + t) * 512 + d] = c;
        }
        gridbar(bar); bar++;
    }
}

extern "C" __global__ void __launch_bounds__(NT, 1) cond_lstm(P p) {
    extern __shared__ char smem[];
    if (blockIdx.x < NGATE) gate_role(p, smem, blockIdx.x, threadIdx.x);
    else                    att_role(p, smem, blockIdx.x, threadIdx.x);
}

#define SMEM_BYTES 163968

extern "C" void kernel_launch(void* const* d_in, const int* in_sizes, int n_in,
                              void* d_out, int out_size) {
    (void)in_sizes; (void)n_in; (void)out_size;
    P p;
    p.X     = (const float*)d_in[0];
    p.ctx   = (const float*)d_in[1];
    p.mask  = (const float*)d_in[2];
    p.cmask = (const int*)d_in[3];
    for (int g = 0; g < 4; ++g) {
        p.W[g]  = (const float*)d_in[4 + 4 * g];
        p.U[g]  = (const float*)d_in[5 + 4 * g];
        p.C[g]  = (const float*)d_in[6 + 4 * g];
        p.bs[g] = (const float*)d_in[7 + 4 * g];
    }
    p.w1c = (const float*)d_in[20];
    p.w1h = (const float*)d_in[21];
    p.b1  = (const float*)d_in[22];
    p.w2  = (const float*)d_in[23];
    p.b2  = (const float*)d_in[24];
    float* out = (float*)d_out;
    p.oh   = out;
    p.oc   = out + 32 * 128 * 512;
    p.octx = out + 2 * 32 * 128 * 512;

    cudaFuncSetAttribute(cond_lstm, cudaFuncAttributeMaxDynamicSharedMemorySize, SMEM_BYTES);
    cond_lstm<<<NBLK, NT, SMEM_BYTES>>>(p);
}

// round 9
// speedup vs baseline: 1.6036x; 1.0812x over previous
#include <cuda_runtime.h>

#define NBLK 144
#define NGATE 128
#define NT 1024

__device__ float g_ct[524288];   // [B=32][L=64][A=256]
__device__ float g_h[16384];     // [32][512]
__device__ float g_c[16384];
__device__ float g_cv[16384];
__device__ unsigned g_flag[NBLK * 8];   // monotonic arrival counters (never reset)

struct P {
    const float *X, *ctx, *mask; const int* cmask;
    const float *W[4], *U[4], *C[4], *bs[4];
    const float *w1c, *w1h, *b1, *w2, *b2;
    float *oh, *oc, *octx;
};

typedef unsigned long long ull;

__device__ __forceinline__ float fsig(float x)  { return 1.f / (1.f + __expf(-x)); }
__device__ __forceinline__ float ftanh(float x) { return 1.f - 2.f / (1.f + __expf(2.f * x)); }
__device__ __forceinline__ float tanha(float x) { float y; asm("tanh.approx.f32 %0, %1;" : "=f"(y) : "f"(x)); return y; }
__device__ __forceinline__ ull fpack(float lo, float hi) {
    ull r; asm("mov.b64 %0, {%1, %2};" : "=l"(r) : "f"(lo), "f"(hi)); return r;
}
__device__ __forceinline__ ull fpack1(float v) {
    ull r; asm("mov.b64 %0, {%1, %1};" : "=l"(r) : "f"(v)); return r;
}
__device__ __forceinline__ void funpack(ull v, float& lo, float& hi) {
    asm("mov.b64 {%0, %1}, %2;" : "=f"(lo), "=f"(hi) : "l"(v));
}
__device__ __forceinline__ void fma2(ull& acc, ull a, ull b) {
    asm("fma.rn.f32x2 %0, %1, %2, %0;" : "+l"(acc) : "l"(a), "l"(b));
}

// Distributed monotonic flag barrier. fv = base + n; arrival = own-slot store,
// release = all 144 flags >= fv. Flags are never reset: at every launch
// boundary all flags are equal (each block's final write is base+257), so the
// next launch's base read is uniform. No reset -> no reset/poll race.
__device__ __forceinline__ void gridbar(unsigned fv) {
    __syncthreads();
    if (threadIdx.x < 32) {
        if (threadIdx.x == 0) {
            __threadfence();
            *(volatile unsigned*)&g_flag[blockIdx.x * 8] = fv;
        }
        for (;;) {
            bool ok = true;
            #pragma unroll
            for (int j = 0; j < 5; ++j) {
                int bk = threadIdx.x + j * 32;
                if (bk < NBLK) ok &= (*(volatile unsigned*)&g_flag[bk * 8] >= fv);
            }
            if (__all_sync(0xffffffffu, ok)) break;
            __nanosleep(32);
        }
        __threadfence();
    }
    __syncthreads();
}

// prologue ctx_trans; csm[512], rsm[4*260]
__device__ void ct_task(const P& p, float* csm, float* rsm, int blk, int tid) {
    const int a = tid & 255, kq = tid >> 8;   // kq 0..3
    for (int tt = blk; tt < 2048; tt += NBLK) {
        int b = tt >> 6, l = tt & 63;
        __syncthreads();
        if (tid < 512) csm[tid] = p.ctx[(b * 64 + l) * 512 + tid];
        __syncthreads();
        float acc = 0.f;
        #pragma unroll 8
        for (int i = 0; i < 128; ++i) {
            int k = kq * 128 + i;
            acc = fmaf(p.w1c[k * 256 + a], csm[k], acc);
        }
        rsm[kq * 260 + a] = acc;
        __syncthreads();
        if (tid < 256)
            g_ct[(b * 64 + l) * 256 + tid] =
                rsm[tid] + rsm[260 + tid] + rsm[520 + tid] + rsm[780 + tid] + p.b1[tid];
        __syncthreads();
    }
}

// stage 32x512 rows into vs[32][513]
__device__ __forceinline__ void gstage(float* vs, const float* src, int stride, int tid) {
    __syncthreads();
    #pragma unroll
    for (int j = 0; j < 4; ++j) {
        int i4 = tid + j * NT;
        int bb = i4 >> 7;
        int k4 = (i4 & 127) * 4;
        float4 v = __ldcg((const float4*)(src + bb * stride + k4));
        float* d = vs + bb * 513 + k4;
        d[0] = v.x; d[1] = v.y; d[2] = v.z; d[3] = v.w;
    }
    __syncthreads();
}

// 16 k per thread; acc: 8 packed f32x2 pairs (gate g -> acc[2g]=(x,y), acc[2g+1]=(z,w))
__device__ __forceinline__ void gpass(ull acc[8], const float* vs, const float* wsm,
                                      int kq, int b) {
    const float* vb = vs + b * 513;
    #pragma unroll 4
    for (int i = 0; i < 16; ++i) {
        int k = i * 32 + kq;
        ull vv = fpack1(vb[k]);
        #pragma unroll
        for (int g = 0; g < 4; ++g) {
            ulonglong2 w = *(const ulonglong2*)(wsm + (g * 512 + k) * 4);
            fma2(acc[g * 2],     w.x, vv);
            fma2(acc[g * 2 + 1], w.y, vv);
        }
    }
}

__device__ void gate_role(const P& p, char* smem, int blk, int tid, unsigned base) {
    float* wsm = (float*)smem;        // 24576 f [mat][g][k][4]
    float* vs  = wsm + 24576;         // 16416 f [32][513]
    float* red = vs;                  // alias
    float* csm = vs;                  // prologue alias
    float* rsm = vs + 512;
    const int hc = blk, b = tid & 31, kq = tid >> 5;   // kq 0..31

    for (int i = tid; i < 24576; i += NT) {
        int j = i & 3, k = (i >> 2) & 511, g = (i >> 11) & 3, m = i >> 13;
        const float* s = (m == 0) ? p.W[g] : (m == 1) ? p.U[g] : p.C[g];
        wsm[i] = s[k * 512 + hc * 4 + j];
    }
    int zi = blk * NT + tid;
    if (zi < 16384) { g_h[zi] = 0.f; g_c[zi] = 0.f; }
    ct_task(p, csm, rsm, blk, tid);
    gridbar(base + 1);

    ull b0[8];
    #pragma unroll
    for (int g = 0; g < 4; ++g) {
        float4 bf = *(const float4*)(p.bs[g] + hc * 4);
        b0[g * 2]     = fpack(bf.x, bf.y);
        b0[g * 2 + 1] = fpack(bf.z, bf.w);
    }
    const ull zz = fpack(0.f, 0.f);

    unsigned bar = base + 2;
    for (int t = 0; t < 128; ++t) {
        gstage(vs, p.X + t * 512, 65536, tid);    // pre-stage X(t) behind barrier wait
        gridbar(bar); bar++;                      // h,c,cv of t-1 sealed
        ull acc[8];
        #pragma unroll
        for (int q = 0; q < 8; ++q) acc[q] = (kq == 0) ? b0[q] : zz;
        gpass(acc, vs, wsm, kq, b);               // x_t @ W
        gstage(vs, g_h, 512, tid);
        gpass(acc, vs, wsm + 8192, kq, b);        // h @ U
        gridbar(bar); bar++;                      // cv ready
        gstage(vs, g_cv, 512, tid);
        gpass(acc, vs, wsm + 16384, kq, b);       // cv @ C
        __syncthreads();
        float av4[4][4];
        #pragma unroll
        for (int g = 0; g < 4; ++g) {
            funpack(acc[g * 2],     av4[g][0], av4[g][1]);
            funpack(acc[g * 2 + 1], av4[g][2], av4[g][3]);
        }
        // two-phase reduction over kq (32 -> 16 -> final)
        if (kq >= 16) {
            int q = kq - 16;
            #pragma unroll
            for (int g = 0; g < 4; ++g)
                #pragma unroll
                for (int j = 0; j < 4; ++j)
                    red[((g * 4 + j) * 16 + q) * 33 + b] = av4[g][j];
        }
        __syncthreads();
        if (kq < 16) {
            #pragma unroll
            for (int g = 0; g < 4; ++g)
                #pragma unroll
                for (int j = 0; j < 4; ++j)
                    red[((g * 4 + j) * 16 + kq) * 33 + b] += av4[g][j];
        }
        __syncthreads();
        if (tid < 128) {
            int bb = tid >> 2, j = tid & 3, h = hc * 4 + j;
            float pre[4];
            #pragma unroll
            for (int g = 0; g < 4; ++g) {
                int o = g * 4 + j;
                float s = 0.f;
                #pragma unroll
                for (int q = 0; q < 16; ++q) s += red[(o * 16 + q) * 33 + bb];
                pre[g] = s;
            }
            float iv = fsig(pre[0]), fv = fsig(pre[1]);
            float gv = ftanh(pre[2]), ov = fsig(pre[3]);
            float co = __ldcg(&g_c[bb * 512 + h]), ho = __ldcg(&g_h[bb * 512 + h]);
            float cn = fv * co + iv * gv;
            float hn = ov * ftanh(cn);
            float m = p.mask[bb * 128 + t];
            hn = (1.f - m) * ho + m * hn;
            cn = (1.f - m) * co + m * cn;
            g_h[bb * 512 + h] = hn;
            g_c[bb * 512 + h] = cn;
            p.oh[(bb * 128 + t) * 512 + h] = hn;
            p.oc[(bb * 128 + t) * 512 + h] = cn;
        }
    }
}

__device__ void att_role(const P& p, char* smem, int blk, int tid, unsigned base) {
    float* ctsm = (float*)smem;       // 32768 f [2][64][256]
    float* hsm  = ctsm + 32768;       // 1024
    float* redh = hsm + 1024;         // 4128: [2][8][258]
    float* hwsm = redh + 4128;        // 512: [2][256]
    float* w2sm = hwsm + 512;         // 256
    float* esm  = w2sm + 256;         // 128
    float* av   = esm + 128;          // 128
    float* ssum = av + 128;           // 16
    float* csm  = ctsm;               // prologue alias
    float* rsm  = ctsm + 512;
    const int b0 = (blk - NGATE) * 2;
    const int a2 = tid & 127, kq = tid >> 7;   // kq 0..7
    const int ww = tid >> 5, lane = tid & 31;

    ct_task(p, csm, rsm, blk, tid);
    gridbar(base + 1);
    for (int i = tid; i < 32768; i += NT) ctsm[i] = __ldcg(&g_ct[b0 * 16384 + i]);
    if (tid < 256) w2sm[tid] = p.w2[tid];
    const float b2v = p.b2[0];

    unsigned bar = base + 2;
    for (int t = 0; t < 128; ++t) {
        gridbar(bar); bar++;
        hsm[tid] = __ldcg(&g_h[b0 * 512 + tid]);
        __syncthreads();
        // hW: thread (a2, kq): f32x2 over a-pair a2, k = i*8+kq
        ull ac0 = fpack(0.f, 0.f), ac1 = fpack(0.f, 0.f);
        #pragma unroll 8
        for (int i = 0; i < 64; ++i) {
            int k = i * 8 + kq;
            ull w = __ldg((const ull*)(p.w1h + k * 256 + a2 * 2));
            fma2(ac0, w, fpack1(hsm[k]));
            fma2(ac1, w, fpack1(hsm[512 + k]));
        }
        {
            float x, y;
            funpack(ac0, x, y);
            redh[kq * 258 + a2 * 2] = x;  redh[kq * 258 + a2 * 2 + 1] = y;
            funpack(ac1, x, y);
            redh[2064 + kq * 258 + a2 * 2] = x;  redh[2064 + kq * 258 + a2 * 2 + 1] = y;
        }
        __syncthreads();
        if (tid < 512) {
            int bb = tid >> 8, a = tid & 255;
            float s = 0.f;
            #pragma unroll
            for (int q = 0; q < 8; ++q) s += redh[bb * 2064 + q * 258 + a];
            hwsm[bb * 256 + a] = s;
        }
        __syncthreads();
        // scores: warp ww -> bb = ww>>4, l = (ww&15)*4 + lq ; tanh.approx
        {
            int bb = ww >> 4;
            #pragma unroll
            for (int lq = 0; lq < 4; ++lq) {
                int l = (ww & 15) * 4 + lq;
                float s = 0.f;
                #pragma unroll
                for (int j = 0; j < 8; ++j) {
                    int a = j * 32 + lane;
                    float x = ctsm[(bb * 64 + l) * 256 + a] + hwsm[bb * 256 + a];
                    s = fmaf(tanha(x), w2sm[a], s);
                }
                #pragma unroll
                for (int o = 16; o; o >>= 1) s += __shfl_xor_sync(0xffffffffu, s, o);
                if (lane == 0)
                    esm[bb * 64 + l] = __expf(s + b2v) * (float)__ldg(&p.cmask[(b0 + bb) * 64 + l]);
            }
        }
        __syncthreads();
        if (tid < 2) {
            float s = 0.f;
            for (int l = 0; l < 64; ++l) s += esm[tid * 64 + l];
            ssum[tid] = s;
        }
        __syncthreads();
        if (tid < 128) av[tid] = esm[tid] / ssum[tid >> 6];
        __syncthreads();
        // ctx_vec: thread owns (bb = tid>>9, d = tid&511)
        {
            int bb = tid >> 9, d = tid & 511;
            float c = 0.f;
            const float* cp = p.ctx + ((b0 + bb) * 64) * 512 + d;
            const float* ap = av + bb * 64;
            #pragma unroll 8
            for (int l = 0; l < 64; ++l)
                c = fmaf(ap[l], __ldg(cp + l * 512), c);
            g_cv[(b0 + bb) * 512 + d] = c;
            p.octx[((b0 + bb) * 128 + t) * 512 + d] = c;
        }
        gridbar(bar); bar++;
    }
}

extern "C" __global__ void __launch_bounds__(NT, 1) cond_lstm(P p) {
    extern __shared__ char smem[];
    // uniform per-block base; all blocks' flags are equal at launch boundaries
    const unsigned base = *(volatile unsigned*)&g_flag[blockIdx.x * 8];
    if (blockIdx.x < NGATE) gate_role(p, smem, blockIdx.x, threadIdx.x, base);
    else                    att_role(p, smem, blockIdx.x, threadIdx.x, base);
}

#define SMEM_BYTES 163968

extern "C" void kernel_launch(void* const* d_in, const int* in_sizes, int n_in,
                              void* d_out, int out_size) {
    (void)in_sizes; (void)n_in; (void)out_size;
    P p;
    p.X     = (const float*)d_in[0];
    p.ctx   = (const float*)d_in[1];
    p.mask  = (const float*)d_in[2];
    p.cmask = (const int*)d_in[3];
    for (int g = 0; g < 4; ++g) {
        p.W[g]  = (const float*)d_in[4 + 4 * g];
        p.U[g]  = (const float*)d_in[5 + 4 * g];
        p.C[g]  = (const float*)d_in[6 + 4 * g];
        p.bs[g] = (const float*)d_in[7 + 4 * g];
    }
    p.w1c = (const float*)d_in[20];
    p.w1h = (const float*)d_in[21];
    p.b1  = (const float*)d_in[22];
    p.w2  = (const float*)d_in[23];
    p.b2  = (const float*)d_in[24];
    float* out = (float*)d_out;
    p.oh   = out;
    p.oc   = out + 32 * 128 * 512;
    p.octx = out + 2 * 32 * 128 * 512;

    cudaFuncSetAttribute(cond_lstm, cudaFuncAttributeMaxDynamicSharedMemorySize, SMEM_BYTES);
    cond_lstm<<<NBLK, NT, SMEM_BYTES>>>(p);
}